// round 9
// baseline (speedup 1.0000x reference)
#include <cuda_runtime.h>
#include <math.h>

typedef unsigned long long u64;

// ---------------- device globals (scratch; no allocation allowed) ----------
__device__ float    g_min = INFINITY;    // idempotent across replays
__device__ float    g_max = -INFINITY;
__device__ double   g_sum = 0.0;         // reset by finalize each run
__device__ unsigned g_cnt = 0;

// ---------------- constants -------------------------------------------------
#define IMG_H 512
#define IMG_W 512
#define N_IMG 48
#define OUT_H 502
#define OUT_W 502
#define NSTRIPS 3
#define RSTRIP 168          // 3*168 >= 502
#define NGROUPS 42          // RSTRIP/4, divisible by 3
#define VBW 528             // padded smem row width
#define MMB 1536

// Gaussian 11-tap weights (sigma=1.5, normalized). Literal macro so scalar
// fmaf becomes FFMA-imm (rt_SMSP=1).
#define WW(j) ((j)==0 ? 0.00102838f : \
               (j)==1 ? 0.00759877f : \
               (j)==2 ? 0.03600077f : \
               (j)==3 ? 0.10936069f : \
               (j)==4 ? 0.21300553f : \
               (j)==5 ? 0.26601173f : \
               (j)==6 ? 0.21300553f : \
               (j)==7 ? 0.10936069f : \
               (j)==8 ? 0.03600077f : \
               (j)==9 ? 0.00759877f : 0.00102838f)

// ---------------- packed f32x2 helpers (sm_103a) -----------------------------
__device__ __forceinline__ u64 pk2(float lo, float hi) {
    u64 r; asm("mov.b64 %0, {%1, %2};" : "=l"(r) : "f"(lo), "f"(hi)); return r;
}
__device__ __forceinline__ void upk2(u64 v, float& lo, float& hi) {
    asm("mov.b64 {%0, %1}, %2;" : "=f"(lo), "=f"(hi) : "l"(v));
}
__device__ __forceinline__ u64 fma2(u64 a, u64 b, u64 c) {
    u64 d; asm("fma.rn.f32x2 %0, %1, %2, %3;" : "=l"(d) : "l"(a), "l"(b), "l"(c));
    return d;
}

// ---------------- atomic float min/max helpers --------------------------------
__device__ __forceinline__ void atomicMaxF(float* a, float v) {
    if (v >= 0.0f) atomicMax((int*)a, __float_as_int(v));
    else           atomicMin((unsigned int*)a, __float_as_uint(v));
}
__device__ __forceinline__ void atomicMinF(float* a, float v) {
    if (v >= 0.0f) atomicMin((int*)a, __float_as_int(v));
    else           atomicMax((unsigned int*)a, __float_as_uint(v));
}

// ---------------- kernel 1: min/max with direct global atomics ---------------
__global__ __launch_bounds__(256)
void minmax_part_kernel(const float4* __restrict__ x) {
    const int t = blockIdx.x * 256 + threadIdx.x;
    const int stride = MMB * 256;
    float4 v[8];
    #pragma unroll
    for (int k = 0; k < 8; k++) v[k] = x[t + k * stride];

    float vmin = INFINITY, vmax = -INFINITY;
    #pragma unroll
    for (int k = 0; k < 8; k++) {
        vmin = fminf(vmin, fminf(fminf(v[k].x, v[k].y), fminf(v[k].z, v[k].w)));
        vmax = fmaxf(vmax, fmaxf(fmaxf(v[k].x, v[k].y), fmaxf(v[k].z, v[k].w)));
    }
    #pragma unroll
    for (int o = 16; o > 0; o >>= 1) {
        vmin = fminf(vmin, __shfl_down_sync(0xffffffffu, vmin, o));
        vmax = fmaxf(vmax, __shfl_down_sync(0xffffffffu, vmax, o));
    }
    __shared__ float smin[8], smax[8];
    int lane = threadIdx.x & 31, wid = threadIdx.x >> 5;
    if (lane == 0) { smin[wid] = vmin; smax[wid] = vmax; }
    __syncthreads();
    if (wid == 0) {
        vmin = (lane < 8) ? smin[lane] : INFINITY;
        vmax = (lane < 8) ? smax[lane] : -INFINITY;
        #pragma unroll
        for (int o = 4; o > 0; o >>= 1) {
            vmin = fminf(vmin, __shfl_down_sync(0xffffffffu, vmin, o));
            vmax = fmaxf(vmax, __shfl_down_sync(0xffffffffu, vmax, o));
        }
        if (lane == 0) { atomicMinF(&g_min, vmin); atomicMaxF(&g_max, vmax); }
    }
}

// ---------------- vertical FIR: packed f32x2, static mod-12 ring --------------
template<int PH>
__device__ __forceinline__ void vert4p(
    const float (&xv)[4], const float (&yv)[4],
    u64 (&pAB)[12], u64 (&pQR)[12], const u64 (&W2)[11],
    float* __restrict__ smA, float* __restrict__ smB,
    float* __restrict__ smQ, float* __restrict__ smR, int tid)
{
    #pragma unroll
    for (int s = 0; s < 4; s++) {
        const int P = (PH + s) % 12;
        float x = xv[s], y = yv[s];
        u64 pxy = pk2(x, y);
        float q = fmaf(y, y, x * x);
        float r = x * y;
        u64 pqr = pk2(q, r);
        #pragma unroll
        for (int j = 0; j < 11; j++) {
            const int sl = (P - j + 24) % 12;
            pAB[sl] = fma2(W2[j], pxy, pAB[sl]);
            pQR[sl] = fma2(W2[j], pqr, pQR[sl]);
        }
        const int fs = (P + 2) % 12;       // completed output row slot
        float a, b, qq, rr;
        upk2(pAB[fs], a, b);   pAB[fs] = 0ull;
        upk2(pQR[fs], qq, rr); pQR[fs] = 0ull;
        smA[s * VBW + tid] = a;
        smB[s * VBW + tid] = b;
        smQ[s * VBW + tid] = qq;
        smR[s * VBW + tid] = rr;
    }
}

// ---------------- horizontal 11-tap over one scalar smem map -----------------
__device__ __forceinline__ void hblur4(const float* __restrict__ sm, int base,
                                       float (&h)[4])
{
    const float4* p = (const float4*)(sm + base);
    float4 q0 = p[0], q1 = p[1], q2 = p[2], q3 = p[3];
    float v[16] = {q0.x, q0.y, q0.z, q0.w, q1.x, q1.y, q1.z, q1.w,
                   q2.x, q2.y, q2.z, q2.w, q3.x, q3.y, q3.z, q3.w};
    #pragma unroll
    for (int off = 0; off < 4; off++) {
        float acc = 0.0f;
        #pragma unroll
        for (int k = 0; k < 11; k++)
            acc = fmaf(WW(k), v[off + k], acc);
        h[off] = acc;
    }
}

// ---------------- one group ---------------------------------------------------
template<int PH>
__device__ __forceinline__ void group_body(
    int gg, int rows_base,
    const float* __restrict__ xi, const float* __restrict__ yi,
    float (&xv)[4], float (&yv)[4],
    u64 (&pAB)[12], u64 (&pQR)[12], const u64 (&W2)[11],
    float* __restrict__ dsm,
    int tid, int hrow, int c0, float C1, float C2, float& tsum)
{
    // ping-pong buffer for this group
    float* bb = dsm + (size_t)(gg & 1) * (4 * 4 * VBW);
    float* smA = bb;
    float* smB = bb + 4 * VBW;
    float* smQ = bb + 8 * VBW;
    float* smR = bb + 12 * VBW;

    vert4p<PH>(xv, yv, pAB, pQR, W2, smA, smB, smQ, smR, tid);
    __syncthreads();

    // prefetch next group's 4 input rows (registers; hidden under horizontal)
    if (gg + 1 < NGROUPS) {
        #pragma unroll
        for (int s = 0; s < 4; s++) {
            int gr = rows_base + 14 + gg * 4 + s;
            bool ok = gr < IMG_H;
            int idx = gr * IMG_W + tid;
            xv[s] = ok ? xi[idx] : 0.0f;
            yv[s] = ok ? yi[idx] : 0.0f;
        }
    }

    float h1[4], h2[4], hq[4], hr[4];
    int base = hrow * VBW + c0;
    hblur4(smA, base, h1);
    hblur4(smB, base, h2);
    hblur4(smQ, base, hq);
    hblur4(smR, base, hr);

    int orow = rows_base + gg * 4 + hrow;
    if (orow < OUT_H) {
        #pragma unroll
        for (int off = 0; off < 4; off++) {
            if (c0 + off < OUT_W) {
                float m1 = h1[off], m2 = h2[off];
                float m1sq = m1 * m1;
                float musq = fmaf(m2, m2, m1sq);
                float m12  = m1 * m2;
                float v1 = 2.0f * (hr[off] - m12) + C2;
                float v2 = (hq[off] - musq) + C2;
                float num = (2.0f * m12 + C1) * v1;
                float den = (musq + C1) * v2;
                tsum += __fdividef(num, den);
            }
        }
    }
    // no trailing sync: next group writes the OTHER buffer; the sync after its
    // vertical pass orders this group's reads before any overwrite.
}

// ---------------- kernel 2: row-streaming SSIM --------------------------------
__global__ __launch_bounds__(512, 1)
void ssim_stream_kernel(const float* __restrict__ xg,
                        const float* __restrict__ yg,
                        float* __restrict__ out)
{
    extern __shared__ float dsm[];           // 2 buffers x 4 maps x 4*VBW
    __shared__ float warp_part[16];

    const int tid   = threadIdx.x;
    const int strip = blockIdx.x;
    const int img   = blockIdx.y;
    const int rows_base = strip * RSTRIP;

    const float* __restrict__ xi = xg + (size_t)img * (IMG_H * IMG_W);
    const float* __restrict__ yi = yg + (size_t)img * (IMG_H * IMG_W);

    const float L  = g_max - g_min;
    const float C1 = (0.01f * L) * (0.01f * L);
    const float C2 = (0.03f * L) * (0.03f * L);

    // packed tap weights; only 6 unique constants -> CSE dedups registers
    u64 W2[11];
    #pragma unroll
    for (int k = 0; k < 11; k++) W2[k] = pk2(WW(k), WW(k));

    u64 pAB[12], pQR[12];
    #pragma unroll
    for (int j = 0; j < 12; j++) { pAB[j] = 0ull; pQR[j] = 0ull; }

    // ---- prologue: input rows 0..9 (static slots, no flush) ----
    {
        float px[10], py[10];
        #pragma unroll
        for (int t = 0; t < 10; t++) {
            int idx = (rows_base + t) * IMG_W + tid;
            px[t] = xi[idx];
            py[t] = yi[idx];
        }
        #pragma unroll
        for (int t = 0; t < 10; t++) {
            float x = px[t], y = py[t];
            u64 pxy = pk2(x, y);
            float q = fmaf(y, y, x * x);
            float r = x * y;
            u64 pqr = pk2(q, r);
            #pragma unroll
            for (int j = 0; j < 10; j++) {
                if (j <= t) {
                    const int sl = t - j;    // (c-j) mod 12 for c=t<10
                    pAB[sl] = fma2(W2[j], pxy, pAB[sl]);
                    pQR[sl] = fma2(W2[j], pqr, pQR[sl]);
                }
            }
        }
    }

    const int hrow = tid >> 7;          // 0..3
    const int c0   = (tid & 127) * 4;   // 0..508
    float tsum = 0.0f;

    // preload group 0's input rows 10..13 (always in-bounds)
    float xv[4], yv[4];
    #pragma unroll
    for (int s = 0; s < 4; s++) {
        int idx = (rows_base + 10 + s) * IMG_W + tid;
        xv[s] = xi[idx];
        yv[s] = yi[idx];
    }

    // main loop: 14 macro-iterations x 3 groups (phases 10, 2, 6)
    for (int m = 0; m < NGROUPS / 3; m++) {
        int gg = m * 3;
        group_body<10>(gg + 0, rows_base, xi, yi, xv, yv, pAB, pQR, W2,
                       dsm, tid, hrow, c0, C1, C2, tsum);
        group_body<2> (gg + 1, rows_base, xi, yi, xv, yv, pAB, pQR, W2,
                       dsm, tid, hrow, c0, C1, C2, tsum);
        group_body<6> (gg + 2, rows_base, xi, yi, xv, yv, pAB, pQR, W2,
                       dsm, tid, hrow, c0, C1, C2, tsum);
    }

    // ---- block reduction into global double sum ----
    #pragma unroll
    for (int o = 16; o > 0; o >>= 1)
        tsum += __shfl_down_sync(0xffffffffu, tsum, o);
    int lane = tid & 31, wid = tid >> 5;
    if (lane == 0) warp_part[wid] = tsum;
    __syncthreads();
    if (wid == 0) {
        float v = (lane < 16) ? warp_part[lane] : 0.0f;
        #pragma unroll
        for (int o = 8; o > 0; o >>= 1)
            v += __shfl_down_sync(0xffffffffu, v, o);
        if (lane == 0) atomicAdd(&g_sum, (double)v);
    }

    // ---- fused finalize: last CTA writes output, resets accumulators ----
    if (tid == 0) {
        __threadfence();
        unsigned old = atomicAdd(&g_cnt, 1u);
        if (old == (unsigned)(NSTRIPS * N_IMG) - 1u) {
            double total = atomicAdd(&g_sum, 0.0);   // coherent read
            const double n = (double)N_IMG * OUT_H * OUT_W;
            out[0] = (float)(-(total / n));
            g_sum = 0.0;                              // reset for next replay
            g_cnt = 0;
        }
    }
}

// ---------------- launcher ----------------------------------------------------
extern "C" void kernel_launch(void* const* d_in, const int* in_sizes, int n_in,
                              void* d_out, int out_size) {
    const float* y_pred = (const float*)d_in[0];
    const float* y_true = (const float*)d_in[1];
    float* out = (float*)d_out;

    const int smem_bytes = 2 * 4 * 4 * VBW * sizeof(float);   // 67584
    cudaFuncSetAttribute(ssim_stream_kernel,
                         cudaFuncAttributeMaxDynamicSharedMemorySize,
                         smem_bytes);

    minmax_part_kernel<<<MMB, 256>>>((const float4*)y_pred);

    dim3 grid(NSTRIPS, N_IMG);
    ssim_stream_kernel<<<grid, 512, smem_bytes>>>(y_pred, y_true, out);
}

// round 10
// speedup vs baseline: 1.1000x; 1.1000x over previous
#include <cuda_runtime.h>
#include <math.h>

// ---------------- device globals (scratch; no allocation allowed) ----------
__device__ float    g_min = INFINITY;    // idempotent across replays
__device__ float    g_max = -INFINITY;
__device__ double   g_sum = 0.0;         // reset by finalize each run
__device__ unsigned g_cnt = 0;
__device__ unsigned g_mmcnt = 0;         // minmax completion counter

// ---------------- constants -------------------------------------------------
#define IMG_H 512
#define IMG_W 512
#define N_IMG 48
#define OUT_H 502
#define OUT_W 502
#define NSTRIPS 3
#define RSTRIP 168          // 3*168 >= 502
#define NGROUPS 42          // RSTRIP/4, divisible by 3
#define VBW 528             // padded smem row width
#define MMB 1536            // minmax blocks (128 threads each)

// Gaussian 11-tap weights (sigma=1.5, normalized). Literal macro so fmaf
// becomes FFMA-imm (rt_SMSP=1, no weight registers).
#define WW(j) ((j)==0 ? 0.00102838f : \
               (j)==1 ? 0.00759877f : \
               (j)==2 ? 0.03600077f : \
               (j)==3 ? 0.10936069f : \
               (j)==4 ? 0.21300553f : \
               (j)==5 ? 0.26601173f : \
               (j)==6 ? 0.21300553f : \
               (j)==7 ? 0.10936069f : \
               (j)==8 ? 0.03600077f : \
               (j)==9 ? 0.00759877f : 0.00102838f)

// ---------------- atomic float min/max helpers --------------------------------
__device__ __forceinline__ void atomicMaxF(float* a, float v) {
    if (v >= 0.0f) atomicMax((int*)a, __float_as_int(v));
    else           atomicMin((unsigned int*)a, __float_as_uint(v));
}
__device__ __forceinline__ void atomicMinF(float* a, float v) {
    if (v >= 0.0f) atomicMin((int*)a, __float_as_int(v));
    else           atomicMax((unsigned int*)a, __float_as_uint(v));
}

// ---------------- kernel 1: min/max (128-thr blocks, co-residency friendly) --
__global__ __launch_bounds__(128)
void minmax_part_kernel(const float4* __restrict__ x) {
    const int t = blockIdx.x * 128 + threadIdx.x;
    const int stride = MMB * 128;              // 196608 float4
    float vmin = INFINITY, vmax = -INFINITY;
    #pragma unroll 2
    for (int h = 0; h < 2; h++) {
        float4 v[8];
        #pragma unroll
        for (int k = 0; k < 8; k++) v[k] = x[t + (h * 8 + k) * stride];
        #pragma unroll
        for (int k = 0; k < 8; k++) {
            vmin = fminf(vmin, fminf(fminf(v[k].x, v[k].y), fminf(v[k].z, v[k].w)));
            vmax = fmaxf(vmax, fmaxf(fmaxf(v[k].x, v[k].y), fmaxf(v[k].z, v[k].w)));
        }
    }
    #pragma unroll
    for (int o = 16; o > 0; o >>= 1) {
        vmin = fminf(vmin, __shfl_down_sync(0xffffffffu, vmin, o));
        vmax = fmaxf(vmax, __shfl_down_sync(0xffffffffu, vmax, o));
    }
    __shared__ float smin[4], smax[4];
    int lane = threadIdx.x & 31, wid = threadIdx.x >> 5;
    if (lane == 0) { smin[wid] = vmin; smax[wid] = vmax; }
    __syncthreads();
    if (threadIdx.x == 0) {
        float mn = smin[0], mx = smax[0];
        #pragma unroll
        for (int i = 1; i < 4; i++) {
            mn = fminf(mn, smin[i]);
            mx = fmaxf(mx, smax[i]);
        }
        atomicMinF(&g_min, mn);
        atomicMaxF(&g_max, mx);
        __threadfence();
        atomicAdd(&g_mmcnt, 1u);
    }
}

// ---------------- vertical FIR: scalar FFMA-imm, static mod-12 ring ----------
template<int PH>
__device__ __forceinline__ void vert4(
    const float (&xv)[4], const float (&yv)[4],
    float (&a1)[12], float (&a2)[12], float (&aq)[12], float (&ar)[12],
    float* __restrict__ smA, float* __restrict__ smB,
    float* __restrict__ smQ, float* __restrict__ smR, int tid)
{
    #pragma unroll
    for (int s = 0; s < 4; s++) {
        const int P = (PH + s) % 12;
        float x = xv[s], y = yv[s];
        float q = fmaf(y, y, x * x);
        float r = x * y;
        #pragma unroll
        for (int j = 0; j < 11; j++) {
            const int sl = (P - j + 24) % 12;
            a1[sl] = fmaf(WW(j), x, a1[sl]);
            a2[sl] = fmaf(WW(j), y, a2[sl]);
            aq[sl] = fmaf(WW(j), q, aq[sl]);
            ar[sl] = fmaf(WW(j), r, ar[sl]);
        }
        const int fs = (P + 2) % 12;       // completed output-row slot
        smA[s * VBW + tid] = a1[fs];  a1[fs] = 0.0f;
        smB[s * VBW + tid] = a2[fs];  a2[fs] = 0.0f;
        smQ[s * VBW + tid] = aq[fs];  aq[fs] = 0.0f;
        smR[s * VBW + tid] = ar[fs];  ar[fs] = 0.0f;
    }
}

// ---------------- horizontal 11-tap over one scalar smem map -----------------
__device__ __forceinline__ void hblur4(const float* __restrict__ sm, int base,
                                       float (&h)[4])
{
    const float4* p = (const float4*)(sm + base);
    float4 q0 = p[0], q1 = p[1], q2 = p[2], q3 = p[3];
    float v[16] = {q0.x, q0.y, q0.z, q0.w, q1.x, q1.y, q1.z, q1.w,
                   q2.x, q2.y, q2.z, q2.w, q3.x, q3.y, q3.z, q3.w};
    #pragma unroll
    for (int off = 0; off < 4; off++) {
        float acc = 0.0f;
        #pragma unroll
        for (int k = 0; k < 11; k++)
            acc = fmaf(WW(k), v[off + k], acc);
        h[off] = acc;
    }
}

// ---------------- one group (ping-pong buffer, single barrier) ----------------
template<int PH>
__device__ __forceinline__ void group_body(
    int gg, int rows_base,
    const float* __restrict__ xi, const float* __restrict__ yi,
    float (&xv)[4], float (&yv)[4],
    float (&a1)[12], float (&a2)[12], float (&aq)[12], float (&ar)[12],
    float* __restrict__ dsm,
    int tid, int hrow, int c0, float C1, float C2, float& tsum)
{
    float* bb  = dsm + (size_t)(gg & 1) * (4 * 4 * VBW);
    float* smA = bb;
    float* smB = bb + 4 * VBW;
    float* smQ = bb + 8 * VBW;
    float* smR = bb + 12 * VBW;

    vert4<PH>(xv, yv, a1, a2, aq, ar, smA, smB, smQ, smR, tid);
    __syncthreads();

    // prefetch next group's 4 input rows (consumed next group -> latency hidden)
    if (gg + 1 < NGROUPS) {
        #pragma unroll
        for (int s = 0; s < 4; s++) {
            int gr = rows_base + 14 + gg * 4 + s;
            bool ok = gr < IMG_H;
            int idx = gr * IMG_W + tid;
            xv[s] = ok ? xi[idx] : 0.0f;
            yv[s] = ok ? yi[idx] : 0.0f;
        }
    }

    float h1[4], h2[4], hq[4], hr[4];
    int base = hrow * VBW + c0;
    hblur4(smA, base, h1);
    hblur4(smB, base, h2);
    hblur4(smQ, base, hq);
    hblur4(smR, base, hr);

    int orow = rows_base + gg * 4 + hrow;
    if (orow < OUT_H) {
        #pragma unroll
        for (int off = 0; off < 4; off++) {
            if (c0 + off < OUT_W) {
                float m1 = h1[off], m2 = h2[off];
                float m1sq = m1 * m1;
                float musq = fmaf(m2, m2, m1sq);     // mu1^2 + mu2^2
                float m12  = m1 * m2;
                float v1 = 2.0f * (hr[off] - m12) + C2;
                float v2 = (hq[off] - musq) + C2;
                float num = (2.0f * m12 + C1) * v1;
                float den = (musq + C1) * v2;
                tsum += __fdividef(num, den);
            }
        }
    }
    // no trailing sync: next group writes the OTHER buffer; its post-vertical
    // sync orders this group's reads before any later overwrite of this buffer.
}

// ---------------- kernel 2: row-streaming SSIM --------------------------------
__global__ __launch_bounds__(512, 1)
void ssim_stream_kernel(const float* __restrict__ xg,
                        const float* __restrict__ yg,
                        float* __restrict__ out)
{
    extern __shared__ float dsm[];           // 2 ping-pong x 4 maps x 4*VBW
    __shared__ float warp_part[16];

    const int tid   = threadIdx.x;
    const int strip = blockIdx.x;
    const int img   = blockIdx.y;
    const int rows_base = strip * RSTRIP;

    const float* __restrict__ xi = xg + (size_t)img * (IMG_H * IMG_W);
    const float* __restrict__ yi = yg + (size_t)img * (IMG_H * IMG_W);

    float a1[12], a2[12], aq[12], ar[12];
    #pragma unroll
    for (int j = 0; j < 12; j++) { a1[j] = a2[j] = aq[j] = ar[j] = 0.0f; }

    // ---- prologue: input rows 0..9 (static slots, no flush) ----
    // Runs concurrently with the minmax kernel (forked stream).
    {
        float px[10], py[10];
        #pragma unroll
        for (int t = 0; t < 10; t++) {
            int idx = (rows_base + t) * IMG_W + tid;
            px[t] = xi[idx];
            py[t] = yi[idx];
        }
        #pragma unroll
        for (int t = 0; t < 10; t++) {
            float x = px[t], y = py[t];
            float q = fmaf(y, y, x * x);
            float r = x * y;
            #pragma unroll
            for (int j = 0; j < 10; j++) {
                if (j <= t) {
                    const int sl = t - j;    // (c-j) mod 12 for c=t<10
                    a1[sl] = fmaf(WW(j), x, a1[sl]);
                    a2[sl] = fmaf(WW(j), y, a2[sl]);
                    aq[sl] = fmaf(WW(j), q, aq[sl]);
                    ar[sl] = fmaf(WW(j), r, ar[sl]);
                }
            }
        }
    }

    const int hrow = tid >> 7;          // 0..3
    const int c0   = (tid & 127) * 4;   // 0..508
    float tsum = 0.0f;

    // preload group 0's input rows 10..13 (always in-bounds)
    float xv[4], yv[4];
    #pragma unroll
    for (int s = 0; s < 4; s++) {
        int idx = (rows_base + 10 + s) * IMG_W + tid;
        xv[s] = xi[idx];
        yv[s] = yi[idx];
    }

    // ---- wait for concurrent minmax before first use of C1/C2 ----
    if (tid == 0) {
        while (atomicAdd(&g_mmcnt, 0u) < (unsigned)MMB) { __nanosleep(64); }
    }
    __syncthreads();
    const float L  = g_max - g_min;
    const float C1 = (0.01f * L) * (0.01f * L);
    const float C2 = (0.03f * L) * (0.03f * L);

    // main loop: 14 macro-iterations x 3 groups (ring phases 10, 2, 6)
    for (int m = 0; m < NGROUPS / 3; m++) {
        int gg = m * 3;
        group_body<10>(gg + 0, rows_base, xi, yi, xv, yv, a1, a2, aq, ar,
                       dsm, tid, hrow, c0, C1, C2, tsum);
        group_body<2> (gg + 1, rows_base, xi, yi, xv, yv, a1, a2, aq, ar,
                       dsm, tid, hrow, c0, C1, C2, tsum);
        group_body<6> (gg + 2, rows_base, xi, yi, xv, yv, a1, a2, aq, ar,
                       dsm, tid, hrow, c0, C1, C2, tsum);
    }

    // ---- block reduction into global double sum ----
    #pragma unroll
    for (int o = 16; o > 0; o >>= 1)
        tsum += __shfl_down_sync(0xffffffffu, tsum, o);
    int lane = tid & 31, wid = tid >> 5;
    if (lane == 0) warp_part[wid] = tsum;
    __syncthreads();
    if (wid == 0) {
        float v = (lane < 16) ? warp_part[lane] : 0.0f;
        #pragma unroll
        for (int o = 8; o > 0; o >>= 1)
            v += __shfl_down_sync(0xffffffffu, v, o);
        if (lane == 0) atomicAdd(&g_sum, (double)v);
    }

    // ---- fused finalize: last CTA writes output, resets counters ----
    if (tid == 0) {
        __threadfence();
        unsigned old = atomicAdd(&g_cnt, 1u);
        if (old == (unsigned)(NSTRIPS * N_IMG) - 1u) {
            double total = atomicAdd(&g_sum, 0.0);   // coherent read
            const double n = (double)N_IMG * OUT_H * OUT_W;
            out[0] = (float)(-(total / n));
            g_sum = 0.0;                              // reset for next replay
            g_cnt = 0;
            g_mmcnt = 0;
            __threadfence();
        }
    }
}

// ---------------- side stream / events (created once at load) -----------------
static cudaStream_t s_side = nullptr;
static cudaEvent_t  s_fork = nullptr, s_join = nullptr;
static bool         s_ok = false;
namespace {
struct SideInit {
    SideInit() {
        bool ok = (cudaStreamCreateWithFlags(&s_side, cudaStreamNonBlocking)
                   == cudaSuccess);
        ok = ok && (cudaEventCreateWithFlags(&s_fork, cudaEventDisableTiming)
                    == cudaSuccess);
        ok = ok && (cudaEventCreateWithFlags(&s_join, cudaEventDisableTiming)
                    == cudaSuccess);
        s_ok = ok;
    }
} s_side_init;
}

// ---------------- launcher ----------------------------------------------------
extern "C" void kernel_launch(void* const* d_in, const int* in_sizes, int n_in,
                              void* d_out, int out_size) {
    const float* y_pred = (const float*)d_in[0];
    const float* y_true = (const float*)d_in[1];
    float* out = (float*)d_out;

    const int smem_bytes = 2 * 4 * 4 * VBW * sizeof(float);   // 67584
    cudaFuncSetAttribute(ssim_stream_kernel,
                         cudaFuncAttributeMaxDynamicSharedMemorySize,
                         smem_bytes);

    dim3 grid(NSTRIPS, N_IMG);

    if (s_ok) {
        // fork: minmax runs on the side stream, concurrent with ssim
        cudaEventRecord(s_fork, 0);
        cudaStreamWaitEvent(s_side, s_fork, 0);
        minmax_part_kernel<<<MMB, 128, 0, s_side>>>((const float4*)y_pred);
        cudaEventRecord(s_join, s_side);
        // ssim on the main stream: no dependency on minmax (spin-waits inside)
        ssim_stream_kernel<<<grid, 512, smem_bytes>>>(y_pred, y_true, out);
        // join side stream back so the graph/stream sees completion
        cudaStreamWaitEvent(0, s_join, 0);
    } else {
        minmax_part_kernel<<<MMB, 128>>>((const float4*)y_pred);
        ssim_stream_kernel<<<grid, 512, smem_bytes>>>(y_pred, y_true, out);
    }
}